// round 6
// baseline (speedup 1.0000x reference)
#include <cuda_runtime.h>
#include <math.h>

using ull = unsigned long long;

constexpr int T_STEPS = 28;
constexpr int B_TOT   = 16384;
constexpr int X_DIM   = 28;
constexpr int H_DIM   = 100;
constexpr int Z_DIM   = 16;
constexpr int TB      = 64;              // batch rows per block (2 per lane)
constexpr int NBLK    = B_TOT / TB;      // 256
constexpr int NTHR    = 512;             // 16 warps

__device__ float        g_part[NBLK * 2];
__device__ unsigned int g_done;

enum { ACT_LIN = 0, ACT_RELU = 1, ACT_SIG = 2, ACT_SP = 3 };

__device__ __forceinline__ float act_apply(float v, int A) {
    if (A == ACT_RELU) return fmaxf(v, 0.f);
    if (A == ACT_SIG)  return 1.f / (1.f + expf(-v));
    if (A == ACT_SP)   return fmaxf(v, 0.f) + log1pf(expf(-fabsf(v)));
    return v;
}
__device__ __forceinline__ float sigf(float v) { return 1.f / (1.f + expf(-v)); }

// ---- packed f32x2 helpers (rows lane / lane+32 packed in one 64-bit reg) --
__device__ __forceinline__ ull b2(float v) {
    ull r; asm("mov.b64 %0,{%1,%1};" : "=l"(r) : "f"(v)); return r;
}
__device__ __forceinline__ ull fma2(ull a, ull b, ull c) {
    ull d; asm("fma.rn.f32x2 %0,%1,%2,%3;" : "=l"(d) : "l"(a), "l"(b), "l"(c));
    return d;
}
__device__ __forceinline__ float2 unpk(ull v) {
    float2 f; asm("mov.b64 {%0,%1},%2;" : "=f"(f.x), "=f"(f.y) : "l"(v)); return f;
}
__device__ __forceinline__ ull pk(float x, float y) {
    ull r; asm("mov.b64 %0,{%1,%2};" : "=l"(r) : "f"(x), "f"(y)); return r;
}

// ---------------------------------------------------------------------------
// GEMM chunk: NO outputs starting at o0. W must be pre-offset to row o0
// (W_o0 = W + o0*K). K compile-time -> weight offsets become immediates.
// Activations feat-major packed: act_u64[k*32 + lane] = rows (lane, lane+32).
template <int NO, int K4A, int K4B>
__device__ __forceinline__ void gemm_chunk(
    const float* __restrict__ Wo, const float* __restrict__ bias, int o0,
    const float* __restrict__ actA, const float* __restrict__ actB,
    float* __restrict__ out, int act, int lane)
{
    constexpr int K = 4 * (K4A + K4B);
    ull acc[NO];
#pragma unroll
    for (int i = 0; i < NO; i++) acc[i] = 0ull;

    const ull* aA = reinterpret_cast<const ull*>(actA);
#pragma unroll 2
    for (int k4 = 0; k4 < K4A; k4++) {
        const int kk = 4 * k4;
        ull a0 = aA[(kk + 0) * 32 + lane];
        ull a1 = aA[(kk + 1) * 32 + lane];
        ull a2 = aA[(kk + 2) * 32 + lane];
        ull a3 = aA[(kk + 3) * 32 + lane];
#pragma unroll
        for (int i = 0; i < NO; i++) {
            float4 w = *reinterpret_cast<const float4*>(Wo + i * K + kk);
            acc[i] = fma2(b2(w.x), a0, acc[i]);
            acc[i] = fma2(b2(w.y), a1, acc[i]);
            acc[i] = fma2(b2(w.z), a2, acc[i]);
            acc[i] = fma2(b2(w.w), a3, acc[i]);
        }
    }
    if constexpr (K4B > 0) {
        const ull* aB = reinterpret_cast<const ull*>(actB);
#pragma unroll 2
        for (int k4 = 0; k4 < K4B; k4++) {
            const int kk = 4 * k4;
            ull a0 = aB[(kk + 0) * 32 + lane];
            ull a1 = aB[(kk + 1) * 32 + lane];
            ull a2 = aB[(kk + 2) * 32 + lane];
            ull a3 = aB[(kk + 3) * 32 + lane];
#pragma unroll
            for (int i = 0; i < NO; i++) {
                float4 w = *reinterpret_cast<const float4*>(Wo + i * K + 4 * K4A + kk);
                acc[i] = fma2(b2(w.x), a0, acc[i]);
                acc[i] = fma2(b2(w.y), a1, acc[i]);
                acc[i] = fma2(b2(w.z), a2, acc[i]);
                acc[i] = fma2(b2(w.w), a3, acc[i]);
            }
        }
    }
    ull* o64 = reinterpret_cast<ull*>(out);
#pragma unroll
    for (int i = 0; i < NO; i++) {
        float bv = bias[o0 + i];
        float2 v = unpk(acc[i]);
        o64[(o0 + i) * 32 + lane] = pk(act_apply(v.x + bv, act),
                                       act_apply(v.y + bv, act));
    }
}

// Nout = 100 over 16 warps: warps 0-11 -> 6 outs, warps 12-15 -> 7 outs.
template <int K4A, int K4B>
__device__ __forceinline__ void gemm100(
    const float* __restrict__ W, const float* __restrict__ bias,
    const float* __restrict__ aA, const float* __restrict__ aB,
    float* __restrict__ out, int act, int warp, int lane)
{
    constexpr int K = 4 * (K4A + K4B);
    if (warp < 12) {
        const int o0 = warp * 6;
        gemm_chunk<6, K4A, K4B>(W + (size_t)o0 * K, bias, o0, aA, aB, out, act, lane);
    } else {
        const int o0 = 72 + (warp - 12) * 7;
        gemm_chunk<7, K4A, K4B>(W + (size_t)o0 * K, bias, o0, aA, aB, out, act, lane);
    }
}

// Wd3 + fused Bernoulli NLL: 4 outputs, accumulate NLL into register.
__device__ __forceinline__ void wd3_nll(
    const float* __restrict__ W, const float* __restrict__ bias,
    const float* __restrict__ hd2, const float* __restrict__ xs,
    int o0, int lane, float& nll)
{
    ull acc[4];
#pragma unroll
    for (int i = 0; i < 4; i++) acc[i] = 0ull;
    const ull* A = reinterpret_cast<const ull*>(hd2);
    const float* Wo = W + (size_t)o0 * 100;
#pragma unroll 2
    for (int k4 = 0; k4 < 25; k4++) {
        const int kk = 4 * k4;
        ull a0 = A[(kk + 0) * 32 + lane];
        ull a1 = A[(kk + 1) * 32 + lane];
        ull a2 = A[(kk + 2) * 32 + lane];
        ull a3 = A[(kk + 3) * 32 + lane];
#pragma unroll
        for (int i = 0; i < 4; i++) {
            float4 w = *reinterpret_cast<const float4*>(Wo + i * 100 + kk);
            acc[i] = fma2(b2(w.x), a0, acc[i]);
            acc[i] = fma2(b2(w.y), a1, acc[i]);
            acc[i] = fma2(b2(w.z), a2, acc[i]);
            acc[i] = fma2(b2(w.w), a3, acc[i]);
        }
    }
    const ull* Xs = reinterpret_cast<const ull*>(xs);
#pragma unroll
    for (int i = 0; i < 4; i++) {
        float bv = bias[o0 + i];
        float2 v  = unpk(acc[i]);
        float2 xv = unpk(Xs[(o0 + i) * 32 + lane]);
        float p0 = sigf(v.x + bv);
        float p1 = sigf(v.y + bv);
        nll -= xv.x * logf(p0 + 1e-10f) + (1.f - xv.x) * logf(1.f - p0 + 1e-10f);
        nll -= xv.y * logf(p1 + 1e-10f) + (1.f - xv.y) * logf(1.f - p1 + 1e-10f);
    }
}

// ---------------------------------------------------------------------------
// GRU wide pass: NJ gate-rows per gate, 3 gate sets (row offsets 0/100/200),
// accumulate over one activation segment. Wo pre-offset to (j0, col0);
// LDW compile-time so all weight offsets are immediates.
template <int NJ, int LDW>
__device__ __forceinline__ void gru_pass(
    ull* __restrict__ G0, ull* __restrict__ G1, ull* __restrict__ G2,
    const float* __restrict__ Wo, const float* __restrict__ act, int lane)
{
    const ull* A = reinterpret_cast<const ull*>(act);
#pragma unroll 1
    for (int k4 = 0; k4 < 25; k4++) {
        const int kk = 4 * k4;
        ull a0 = A[(kk + 0) * 32 + lane];
        ull a1 = A[(kk + 1) * 32 + lane];
        ull a2 = A[(kk + 2) * 32 + lane];
        ull a3 = A[(kk + 3) * 32 + lane];
#pragma unroll
        for (int jj = 0; jj < NJ; jj++) {
            float4 w;
            w = *reinterpret_cast<const float4*>(Wo + jj * LDW + kk);
            G0[jj] = fma2(b2(w.x), a0, G0[jj]); G0[jj] = fma2(b2(w.y), a1, G0[jj]);
            G0[jj] = fma2(b2(w.z), a2, G0[jj]); G0[jj] = fma2(b2(w.w), a3, G0[jj]);
            w = *reinterpret_cast<const float4*>(Wo + 100 * LDW + jj * LDW + kk);
            G1[jj] = fma2(b2(w.x), a0, G1[jj]); G1[jj] = fma2(b2(w.y), a1, G1[jj]);
            G1[jj] = fma2(b2(w.z), a2, G1[jj]); G1[jj] = fma2(b2(w.w), a3, G1[jj]);
            w = *reinterpret_cast<const float4*>(Wo + 200 * LDW + jj * LDW + kk);
            G2[jj] = fma2(b2(w.x), a0, G2[jj]); G2[jj] = fma2(b2(w.y), a1, G2[jj]);
            G2[jj] = fma2(b2(w.z), a2, G2[jj]); G2[jj] = fma2(b2(w.w), a3, G2[jj]);
        }
    }
}

template <int NJ>
__device__ __forceinline__ void gru_wide(
    int j0,
    const float* __restrict__ Wih, const float* __restrict__ Whh,
    const float* __restrict__ bih, const float* __restrict__ bhh,
    const float* __restrict__ pz, const float* __restrict__ px,
    const float* __restrict__ hc, float* __restrict__ hn, int lane)
{
    ull R[NJ], U[NJ], NI[NJ], NH[NJ];
#pragma unroll
    for (int i = 0; i < NJ; i++) { R[i] = 0; U[i] = 0; NI[i] = 0; NH[i] = 0; }

    // r,u,n_i over [pz ; px] with Wih (ld 200)
    gru_pass<NJ, 200>(R, U, NI, Wih + (size_t)j0 * 200,       pz, lane);
    gru_pass<NJ, 200>(R, U, NI, Wih + (size_t)j0 * 200 + 100, px, lane);
    // r,u,n_h over hc with Whh (ld 100)
    gru_pass<NJ, 100>(R, U, NH, Whh + (size_t)j0 * 100,       hc, lane);

    const ull* h64 = reinterpret_cast<const ull*>(hc);
    ull* hn64 = reinterpret_cast<ull*>(hn);
#pragma unroll
    for (int jj = 0; jj < NJ; jj++) {
        const int j = j0 + jj;
        const float br = bih[j] + bhh[j];
        const float bu = bih[100 + j] + bhh[100 + j];
        const float bn = bih[200 + j];
        const float bm = bhh[200 + j];
        float2 Rv = unpk(R[jj]);
        float2 Uv = unpk(U[jj]);
        float2 Nv = unpk(NI[jj]);
        float2 Mv = unpk(NH[jj]);
        float2 H  = unpk(h64[j * 32 + lane]);
        float rr0 = sigf(Rv.x + br), rr1 = sigf(Rv.y + br);
        float uu0 = sigf(Uv.x + bu), uu1 = sigf(Uv.y + bu);
        float nn0 = tanhf(Nv.x + bn + rr0 * (Mv.x + bm));
        float nn1 = tanhf(Nv.y + bn + rr1 * (Mv.y + bm));
        hn64[j * 32 + lane] = pk((1.f - uu0) * nn0 + uu0 * H.x,
                                 (1.f - uu1) * nn1 + uu1 * H.y);
    }
}

// ---------------------------------------------------------------------------
__global__ void __launch_bounds__(NTHR, 1) vrnn_main(
    const float* __restrict__ x,      const float* __restrict__ eps,
    const float* __restrict__ Wpx,    const float* __restrict__ bpx,
    const float* __restrict__ Wpz,    const float* __restrict__ bpz,
    const float* __restrict__ Wp1,    const float* __restrict__ bp1,
    const float* __restrict__ Wp_mu,  const float* __restrict__ bp_mu,
    const float* __restrict__ Wp_sig, const float* __restrict__ bp_sig,
    const float* __restrict__ We1,    const float* __restrict__ be1,
    const float* __restrict__ We_mu,  const float* __restrict__ be_mu,
    const float* __restrict__ We_sig, const float* __restrict__ be_sig,
    const float* __restrict__ Wd1,    const float* __restrict__ bd1,
    const float* __restrict__ Wd2,    const float* __restrict__ bd2,
    const float* __restrict__ Wd3,    const float* __restrict__ bd3,
    const float* __restrict__ Wih,    const float* __restrict__ Whh,
    const float* __restrict__ bih,    const float* __restrict__ bhh,
    float* __restrict__ out)
{
    extern __shared__ float s[];
    float* xs   = s;                      // 28*64
    float* es   = xs   + X_DIM * TB;      // 16*64 (becomes z in place)
    float* emu  = es   + Z_DIM * TB;
    float* esg  = emu  + Z_DIM * TB;
    float* pmu  = esg  + Z_DIM * TB;
    float* psg  = pmu  + Z_DIM * TB;
    float* hA   = psg  + Z_DIM * TB;      // 100*64
    float* hB   = hA   + H_DIM * TB;      // he / hd1 / hn scratch
    float* px   = hB   + H_DIM * TB;
    float* pz   = px   + H_DIM * TB;
    float* B2   = pz   + H_DIM * TB;      // hp / hd2

    __shared__ int s_last;

    const int tid  = threadIdx.x;
    const int lane = tid & 31;
    const int warp = tid >> 5;
    const int b0   = blockIdx.x * TB;

    for (int i = tid; i < H_DIM * TB; i += NTHR) hA[i] = 0.f;

    float kl_acc = 0.f, nll_acc = 0.f;
    float* hc = hA;
    float* hs = hB;

    for (int t = 0; t < T_STEPS; t++) {
        // ---- stage inputs into packed feat-major layout
        const float* xg = x   + ((size_t)t * B_TOT + b0) * X_DIM;
        const float* eg = eps + ((size_t)t * B_TOT + b0) * Z_DIM;
        for (int i = tid; i < X_DIM * TB; i += NTHR) {
            int r = i / X_DIM, k = i % X_DIM;
            xs[(k * 32 + (r & 31)) * 2 + (r >> 5)] = xg[i];
        }
        for (int i = tid; i < Z_DIM * TB; i += NTHR) {
            int r = i >> 4, k = i & 15;
            es[(k * 32 + (r & 31)) * 2 + (r >> 5)] = eg[i];
        }
        __syncthreads();

        // 1. px = relu(Wpx x + b)                  [100, K=28]
        gemm100<7, 0>(Wpx, bpx, xs, nullptr, px, ACT_RELU, warp, lane);
        __syncthreads();

        // 2||3. he = relu(We1 [px;h]) -> hs  (warps 0-10)
        //       hp = relu(Wp1 h)      -> B2  (warps 11-15)
        if (warp < 10) {
            const int o0 = warp * 9;
            gemm_chunk<9, 25, 25>(We1 + (size_t)o0 * 200, be1, o0, px, hc, hs, ACT_RELU, lane);
        } else if (warp == 10) {
            gemm_chunk<10, 25, 25>(We1 + (size_t)90 * 200, be1, 90, px, hc, hs, ACT_RELU, lane);
        } else {
            const int o0 = (warp - 11) * 20;
            gemm_chunk<20, 25, 0>(Wp1 + (size_t)o0 * 100, bp1, o0, hc, nullptr, B2, ACT_RELU, lane);
        }
        __syncthreads();

        // 4. heads: 4 warps per matrix, 4 outputs each (K=100)
        {
            const int m = warp >> 2, o0 = (warp & 3) * 4;
            if (m == 0)
                gemm_chunk<4, 25, 0>(We_mu  + (size_t)o0 * 100, be_mu,  o0, hs, nullptr, emu, ACT_LIN, lane);
            else if (m == 1)
                gemm_chunk<4, 25, 0>(We_sig + (size_t)o0 * 100, be_sig, o0, hs, nullptr, esg, ACT_SP,  lane);
            else if (m == 2)
                gemm_chunk<4, 25, 0>(Wp_mu  + (size_t)o0 * 100, bp_mu,  o0, B2, nullptr, pmu, ACT_LIN, lane);
            else
                gemm_chunk<4, 25, 0>(Wp_sig + (size_t)o0 * 100, bp_sig, o0, B2, nullptr, psg, ACT_SP,  lane);
        }
        __syncthreads();

        // 5. z = enc_mu + sqrt(enc_sig)*eps  (in place over es)
        for (int i = tid; i < Z_DIM * TB; i += NTHR)
            es[i] = emu[i] + sqrtf(esg[i]) * es[i];
        __syncthreads();

        // 6. pz = relu(Wpz z + b)                  [100, K=16]
        gemm100<4, 0>(Wpz, bpz, es, nullptr, pz, ACT_RELU, warp, lane);
        __syncthreads();

        // 7. hd1 = relu(Wd1 [pz;h]) -> hs          [100, K=200]
        gemm100<25, 25>(Wd1, bd1, pz, hc, hs, ACT_RELU, warp, lane);
        __syncthreads();

        // 8. hd2 = relu(Wd2 hd1) -> B2             [100, K=100]
        gemm100<25, 0>(Wd2, bd2, hs, nullptr, B2, ACT_RELU, warp, lane);
        __syncthreads();

        // 10. GRU wide: one task per warp -> hn into hs
        if (warp < 12)
            gru_wide<6>(warp * 6, Wih, Whh, bih, bhh, pz, px, hc, hs, lane);
        else
            gru_wide<7>(72 + (warp - 12) * 7, Wih, Whh, bih, bhh, pz, px, hc, hs, lane);
        __syncthreads();

        // 9'. Wd3 + fused NLL (warps 0-6) || KL (warps 7-15)
        if (warp < 7) {
            wd3_nll(Wd3, bd3, B2, xs, warp * 4, lane, nll_acc);
        } else {
            const ull* Emu = (const ull*)emu; const ull* Esg = (const ull*)esg;
            const ull* Pmu = (const ull*)pmu; const ull* Psg = (const ull*)psg;
            const int base = tid - 224;           // 288 threads cover 512 items
#pragma unroll
            for (int rep = 0; rep < 2; rep++) {
                const int e = base + rep * 288;
                if (e < Z_DIM * 32) {
                    float2 esv = unpk(Esg[e]);
                    float2 emv = unpk(Emu[e]);
                    float2 pmv = unpk(Pmu[e]);
                    float2 psv = unpk(Psg[e]);
                    {
                        float ps = psv.x + 1e-10f, d = emv.x - pmv.x;
                        kl_acc += 0.5f * (2.f * logf(ps) - 2.f * logf(esv.x)
                                          + (esv.x * esv.x + d * d) / (ps * ps) - 1.f);
                    }
                    {
                        float ps = psv.y + 1e-10f, d = emv.y - pmv.y;
                        kl_acc += 0.5f * (2.f * logf(ps) - 2.f * logf(esv.y)
                                          + (esv.y * esv.y + d * d) / (ps * ps) - 1.f);
                    }
                }
            }
        }

        { float* tmp = hc; hc = hs; hs = tmp; }
        __syncthreads();   // protect xs/es/head buffers before next staging
    }

    // ---- block partial reduction (16 warps)
#pragma unroll
    for (int off = 16; off > 0; off >>= 1) {
        kl_acc  += __shfl_down_sync(0xffffffffu, kl_acc,  off);
        nll_acc += __shfl_down_sync(0xffffffffu, nll_acc, off);
    }
    if (lane == 0) { s[warp] = kl_acc; s[16 + warp] = nll_acc; }
    __syncthreads();
    if (tid == 0) {
        float k = 0.f, n = 0.f;
        for (int w = 0; w < 16; w++) { k += s[w]; n += s[16 + w]; }
        g_part[2 * blockIdx.x + 0] = k;
        g_part[2 * blockIdx.x + 1] = n;
        __threadfence();
        unsigned v = atomicAdd(&g_done, 1u);
        s_last = (v == (unsigned)(gridDim.x - 1)) ? 1 : 0;
    }
    __syncthreads();

    // ---- deterministic final reduction in the last-arriving block
    if (s_last) {
        if (tid < NBLK) {
            s[tid]       = g_part[2 * tid + 0];
            s[512 + tid] = g_part[2 * tid + 1];
        }
        __syncthreads();
        for (int st = NBLK / 2; st > 0; st >>= 1) {
            if (tid < st) { s[tid] += s[tid + st]; s[512 + tid] += s[512 + tid + st]; }
            __syncthreads();
        }
        if (tid == 0) {
            const float invB = 1.f / (float)B_TOT;
            out[0] = s[0] * invB;
            out[1] = s[512] * invB;
            g_done = 0;                  // reset for next graph replay
        }
    }
}

// ---------------------------------------------------------------------------
extern "C" void kernel_launch(void* const* d_in, const int* in_sizes, int n_in,
                              void* d_out, int out_size)
{
    (void)in_sizes; (void)n_in; (void)out_size;
    const float* x      = (const float*)d_in[0];
    const float* eps    = (const float*)d_in[1];
    const float* Wpx    = (const float*)d_in[2];
    const float* bpx    = (const float*)d_in[3];
    const float* Wpz    = (const float*)d_in[4];
    const float* bpz    = (const float*)d_in[5];
    const float* Wp1    = (const float*)d_in[6];
    const float* bp1    = (const float*)d_in[7];
    const float* Wp_mu  = (const float*)d_in[8];
    const float* bp_mu  = (const float*)d_in[9];
    const float* Wp_sig = (const float*)d_in[10];
    const float* bp_sig = (const float*)d_in[11];
    const float* We1    = (const float*)d_in[12];
    const float* be1    = (const float*)d_in[13];
    const float* We_mu  = (const float*)d_in[14];
    const float* be_mu  = (const float*)d_in[15];
    const float* We_sig = (const float*)d_in[16];
    const float* be_sig = (const float*)d_in[17];
    const float* Wd1    = (const float*)d_in[18];
    const float* bd1    = (const float*)d_in[19];
    const float* Wd2    = (const float*)d_in[20];
    const float* bd2    = (const float*)d_in[21];
    const float* Wd3    = (const float*)d_in[22];
    const float* bd3    = (const float*)d_in[23];
    const float* Wih    = (const float*)d_in[24];
    const float* Whh    = (const float*)d_in[25];
    const float* bih    = (const float*)d_in[26];
    const float* bhh    = (const float*)d_in[27];
    float* out = (float*)d_out;

    const int smem_floats =
        X_DIM * TB + 5 * Z_DIM * TB + 5 * H_DIM * TB;   // 38,912
    const int smem_bytes = smem_floats * (int)sizeof(float);   // 155,648 B

    cudaFuncSetAttribute(vrnn_main,
                         cudaFuncAttributeMaxDynamicSharedMemorySize, smem_bytes);

    vrnn_main<<<NBLK, NTHR, smem_bytes>>>(
        x, eps, Wpx, bpx, Wpz, bpz, Wp1, bp1, Wp_mu, bp_mu, Wp_sig, bp_sig,
        We1, be1, We_mu, be_mu, We_sig, be_sig, Wd1, bd1, Wd2, bd2, Wd3, bd3,
        Wih, Whh, bih, bhh, out);
}